// round 3
// baseline (speedup 1.0000x reference)
#include <cuda_runtime.h>
#include <cstdint>

#define TT 256
#define HH 512
#define BB 128
#define KK 1024
#define NGATE 2048
#define GRID 64
#define NTHR 256
#define MT 64
#define NT 128
#define KC 64
#define NKC 16
#define LDSD 68            // padded row stride (floats): 68%32=4 -> conflict-free frags, 272B is 16B-aligned
#define A_FL (MT*LDSD)     // 4352 floats
#define W_FL (NT*LDSD)     // 8704 floats
#define SMEMB ((2*A_FL + 2*W_FL)*4)

#define O_H1F 16777216L
#define O_M0  16908288L
#define O_M1F 33685504L

// ---------------- device scratch (no allocations allowed) ----------------
__device__ __align__(16) float g_Wc[4][NGATE][KK];   // fused [Wih|Whh], gate-interleaved, tf32-rounded
__device__ __align__(16) float g_bias[4][NGATE];
__device__ __align__(16) float g_h0a[BB*HH];
__device__ __align__(16) float g_m0a[BB*HH];
__device__ __align__(16) float g_h1[2][2][BB*HH];    // [layer][parity]
__device__ __align__(16) float g_m1[2][2][BB*HH];
__device__ unsigned g_cnt;
__device__ volatile unsigned g_gen;

// ---------------- helpers ----------------
__device__ __forceinline__ unsigned f2tf(float x) {
    unsigned u; asm("cvt.rna.tf32.f32 %0, %1;" : "=r"(u) : "f"(x)); return u;
}
__device__ __forceinline__ float sigf(float x) { return 1.f / (1.f + __expf(-x)); }

__device__ __forceinline__ void cp16(float* ds, const float* gs) {
    unsigned s = (unsigned)__cvta_generic_to_shared(ds);
    asm volatile("cp.async.cg.shared.global [%0], [%1], 16;" :: "r"(s), "l"(gs));
}
__device__ __forceinline__ void cp_commit() { asm volatile("cp.async.commit_group;"); }
__device__ __forceinline__ void cp_wait1()  { asm volatile("cp.async.wait_group 1;"); }
__device__ __forceinline__ void cp_wait0()  { asm volatile("cp.async.wait_group 0;"); }

// grid barrier: all 64 CTAs resident (grid <= #SMs), deadlock-free
__device__ __forceinline__ void gsync() {
    __threadfence();
    __syncthreads();
    if (threadIdx.x == 0) {
        unsigned g = g_gen;
        if (atomicAdd(&g_cnt, 1u) == GRID - 1) {
            g_cnt = 0;
            __threadfence();
            g_gen = g + 1;
        } else {
            while (g_gen == g) { }
        }
    }
    __syncthreads();
    __threadfence();
}

__device__ __forceinline__ void ldchunk(float* As, float* Ws,
    const float* xp, long xs, const float* hp, long hs,
    const float* wp, int kc)
{
    const float* src; long stride; int kofs;
    if (kc < 8) { src = xp; stride = xs; kofs = kc * KC; }
    else        { src = hp; stride = hs; kofs = kc * KC - 512; }
    int tid = threadIdx.x;
    #pragma unroll
    for (int i = 0; i < 4; ++i) {                 // A: 64 rows x 16 float4
        int idx = tid + i * NTHR; int r = idx >> 4, c4 = idx & 15;
        cp16(&As[r * LDSD + c4 * 4], src + (long)r * stride + kofs + c4 * 4);
    }
    const float* ws = wp + kc * KC;
    #pragma unroll
    for (int i = 0; i < 8; ++i) {                 // W: 128 rows x 16 float4
        int idx = tid + i * NTHR; int r = idx >> 4, c4 = idx & 15;
        cp16(&Ws[r * LDSD + c4 * 4], ws + (long)r * KK + c4 * 4);
    }
}

__device__ __forceinline__ void mma8(float* c, const unsigned* a, const unsigned* b) {
    asm volatile(
        "mma.sync.aligned.m16n8k8.row.col.f32.tf32.tf32.f32 "
        "{%0,%1,%2,%3}, {%4,%5,%6,%7}, {%8,%9}, {%0,%1,%2,%3};"
        : "+f"(c[0]), "+f"(c[1]), "+f"(c[2]), "+f"(c[3])
        : "r"(a[0]), "r"(a[1]), "r"(a[2]), "r"(a[3]), "r"(b[0]), "r"(b[1]));
}

// One fused LSTM cell tile: gates[64 x 128] = [x;h] @ Wc[cell]^T + b, then elementwise.
__device__ void do_cell(float* As0, float* As1, float* Ws0, float* Ws1,
    const float* xp, long xs, const float* hp, long hs,
    const float* cptr, long cs, int cell,
    float* hd, long hds, float* md, long mds,
    int m0, int n0)
{
    const float* wp = &g_Wc[cell][n0][0];
    const float* xq = xp + (long)m0 * xs;
    const float* hq = hp + (long)m0 * hs;
    int w = threadIdx.x >> 5, lane = threadIdx.x & 31;
    int wm = (w & 1) * 32, wn = (w >> 1) * 32;
    int rb = lane >> 2, q = lane & 3;

    float acc[2][4][4];
    #pragma unroll
    for (int i = 0; i < 2; ++i)
        #pragma unroll
        for (int j = 0; j < 4; ++j)
            #pragma unroll
            for (int v = 0; v < 4; ++v) acc[i][j][v] = 0.f;

    ldchunk(As0, Ws0, xq, xs, hq, hs, wp, 0);
    cp_commit();
    for (int kc = 0; kc < NKC; ++kc) {
        __syncthreads();
        if (kc + 1 < NKC) {
            ldchunk((kc & 1) ? As0 : As1, (kc & 1) ? Ws0 : Ws1, xq, xs, hq, hs, wp, kc + 1);
            cp_commit();
            cp_wait1();
        } else {
            cp_wait0();
        }
        __syncthreads();
        float* Ab = (kc & 1) ? As1 : As0;
        float* Wb = (kc & 1) ? Ws1 : Ws0;
        #pragma unroll
        for (int ks = 0; ks < 8; ++ks) {
            int kk = ks * 8;
            unsigned a[2][4], b[4][2];
            #pragma unroll
            for (int i = 0; i < 2; ++i) {
                const float* ap = Ab + (wm + i * 16 + rb) * LDSD + kk + q;
                a[i][0] = f2tf(ap[0]);
                a[i][1] = f2tf(ap[8 * LDSD]);
                a[i][2] = f2tf(ap[4]);
                a[i][3] = f2tf(ap[8 * LDSD + 4]);
            }
            #pragma unroll
            for (int j = 0; j < 4; ++j) {
                const float* bp = Wb + (wn + j * 8 + rb) * LDSD + kk + q;
                b[j][0] = __float_as_uint(bp[0]);    // W pre-rounded to tf32
                b[j][1] = __float_as_uint(bp[4]);
            }
            #pragma unroll
            for (int i = 0; i < 2; ++i)
                #pragma unroll
                for (int j = 0; j < 4; ++j) mma8(acc[i][j], a[i], b[j]);
        }
    }

    // elementwise LSTM: cols 4u..4u+3 are (i,f,g,o) of unit u; pair lanes via shfl_xor 1
    bool ev = !(q & 1);
    #pragma unroll
    for (int i = 0; i < 2; ++i) {
        #pragma unroll
        for (int j = 0; j < 4; ++j) {
            int nc = n0 + wn + j * 8 + q * 2;
            float b0 = g_bias[cell][nc], b1 = g_bias[cell][nc + 1];
            #pragma unroll
            for (int h = 0; h < 2; ++h) {
                float v0 = acc[i][j][2 * h] + b0;
                float v1 = acc[i][j][2 * h + 1] + b1;
                float p0 = __shfl_xor_sync(0xffffffffu, v0, 1);
                float p1 = __shfl_xor_sync(0xffffffffu, v1, 1);
                if (ev) {
                    float ig = v0, fg = v1, gg = p0, og = p1;
                    int mrow = m0 + wm + i * 16 + rb + h * 8;
                    int u = nc >> 2;
                    float cold = cptr ? __ldcg(cptr + (long)mrow * cs + u) : 0.f;
                    float cn = sigf(fg) * cold + sigf(ig) * tanhf(gg);
                    float hn = sigf(og) * tanhf(cn);
                    hd[(long)mrow * hds + u] = hn;
                    md[(long)mrow * mds + u] = cn;
                }
            }
        }
    }
}

// ---------------- main persistent kernel ----------------
__global__ void __launch_bounds__(NTHR, 1) lstm_main(const float* __restrict__ H0, float* __restrict__ out) {
    extern __shared__ float sm[];
    float* As0 = sm;
    float* As1 = sm + A_FL;
    float* Ws0 = sm + 2 * A_FL;
    float* Ws1 = sm + 2 * A_FL + W_FL;

    int cta = blockIdx.x;
    int grp = cta >> 5;                 // 0: first cell of phase, 1: second
    int tl = cta & 31;
    int m0 = (tl & 1) * 64;
    int n0 = (tl >> 1) * 128;
    float* outH0 = out;
    float* outM0 = out + O_M0;
    const long TH = (long)TT * HH;

    for (int ph = 0; ph <= 2 * TT; ++ph) {
        int t = ph >> 1;
        if (!(ph & 1)) {
            if (grp == 0) {
                if (t < TT)   // cell00(t): x=h1[0], h=H0[:,t], c=0 -> h0a,m0a
                    do_cell(As0, As1, Ws0, Ws1,
                            g_h1[0][t & 1], HH, H0 + (long)t * HH, TH,
                            nullptr, 0, 0, g_h0a, HH, g_m0a, HH, m0, n0);
            } else {
                if (t >= 1) { // cell11(t-1): x=outH0[:,t-1], h=h1[1], c=m1[1] -> h1[1],m1[1] (parity flip)
                    int tp = t - 1;
                    do_cell(As0, As1, Ws0, Ws1,
                            outH0 + (long)tp * HH, TH, g_h1[1][tp & 1], HH,
                            g_m1[1][tp & 1], HH, 3,
                            g_h1[1][(tp + 1) & 1], HH, g_m1[1][(tp + 1) & 1], HH, m0, n0);
                }
            }
        } else {
            if (grp == 0) {   // cell01(t): x=h0a, h=h1[0], c=m1[0] -> h1[0],m1[0] (parity flip)
                do_cell(As0, As1, Ws0, Ws1,
                        g_h0a, HH, g_h1[0][t & 1], HH,
                        g_m1[0][t & 1], HH, 1,
                        g_h1[0][(t + 1) & 1], HH, g_m1[0][(t + 1) & 1], HH, m0, n0);
            } else {          // cell10(t): x=h1[1], h=h0a, c=m0a -> out H0_out/M0_out[:,t]
                do_cell(As0, As1, Ws0, Ws1,
                        g_h1[1][t & 1], HH, g_h0a, HH,
                        g_m0a, HH, 2,
                        outH0 + (long)t * HH, TH, outM0 + (long)t * HH, TH, m0, n0);
            }
        }
        gsync();
    }

    // final H1f / M1f (parity 0 holds t=255 results)
    for (int idx = cta * NTHR + threadIdx.x; idx < 2 * BB * HH; idx += GRID * NTHR) {
        int b = idx >> 10, l = (idx >> 9) & 1, j = idx & 511;
        out[O_H1F + idx] = __ldcg(&g_h1[l][0][b * HH + j]);
        out[O_M1F + idx] = __ldcg(&g_m1[l][0][b * HH + j]);
    }
}

// ---------------- prep kernels ----------------
__global__ void prep_w(const float* __restrict__ Wih, const float* __restrict__ Whh) {
    long i = (long)blockIdx.x * blockDim.x + threadIdx.x;
    if (i >= (long)4 * NGATE * KK) return;
    int k = (int)(i & 1023);
    long r = i >> 10;
    int nr = (int)(r & 2047);
    int c = (int)(r >> 11);
    int g = nr & 3, j = nr >> 2;
    long srow = (long)c * NGATE + g * HH + j;
    float v = (k < HH) ? Wih[srow * HH + k] : Whh[srow * HH + (k - HH)];
    unsigned u; asm("cvt.rna.tf32.f32 %0, %1;" : "=r"(u) : "f"(v));
    ((float*)g_Wc)[i] = __uint_as_float(u);
}

__global__ void prep_misc(const float* __restrict__ bih, const float* __restrict__ bhh) {
    int i = blockIdx.x * blockDim.x + threadIdx.x;
    if (i < 2 * 2 * BB * HH) {
        ((float*)g_h1)[i] = 0.f;
        ((float*)g_m1)[i] = 0.f;
    }
    if (i < 4 * NGATE) {
        int nr = i & 2047, c = i >> 11;
        int g = nr & 3, j = nr >> 2;
        long s = (long)c * NGATE + g * HH + j;
        ((float*)g_bias)[i] = bih[s] + bhh[s];
    }
    if (i == 0) { g_cnt = 0; g_gen = 0; }
}

// ---------------- launch ----------------
extern "C" void kernel_launch(void* const* d_in, const int* in_sizes, int n_in,
                              void* d_out, int out_size) {
    const float* H0  = (const float*)d_in[0];
    const float* Wih = (const float*)d_in[1];
    const float* Whh = (const float*)d_in[2];
    const float* bih = (const float*)d_in[3];
    const float* bhh = (const float*)d_in[4];
    float* out = (float*)d_out;

    prep_w<<<32768, 256>>>(Wih, Whh);
    prep_misc<<<1024, 256>>>(bih, bhh);

    cudaFuncSetAttribute(lstm_main, cudaFuncAttributeMaxDynamicSharedMemorySize, SMEMB);
    lstm_main<<<GRID, NTHR, SMEMB>>>(H0, out);
}

// round 5
// speedup vs baseline: 1.1307x; 1.1307x over previous
#include <cuda_runtime.h>
#include <cstdint>

#define TT 256
#define HH 512
#define BB 128
#define KK 1024
#define NGATE 2048
#define GRID 128
#define NTHR 256
#define KC 128                // K per chunk
#define NKC 8
#define LDSD 132              // padded row stride (floats); 528B, 16B-aligned
#define STG_FL (128*LDSD)     // A(64 rows)+W(64 rows) per stage = 16896 floats
#define STG_BY (STG_FL*4)     // 67584 B
#define SMEMB (3*STG_BY)      // 202752 B, 3 stages

#define O_H1F 16777216L
#define O_M0  16908288L
#define O_M1F 33685504L

// ---------------- device scratch ----------------
__device__ __align__(16) float g_Wc[4][NGATE][KK];   // fused [Wih|Whh], gate-interleaved rows, k-permuted, tf32
__device__ __align__(16) float g_bias[4][NGATE];
__device__ __align__(16) float g_H0r[BB*TT*HH];      // H0, k-permuted + tf32-rounded
__device__ __align__(16) float g_h1r[2][2][BB*HH];   // [layer][parity], permuted+rounded (MMA input)
__device__ __align__(16) float g_h1f[2][BB*HH];      // full precision (final output)
__device__ __align__(16) float g_m1[2][BB*HH];       // cell state, full precision
__device__ __align__(16) float g_h0ar[BB*HH];        // A0 h-out (permuted+rounded)
__device__ __align__(16) float g_m0a[BB*HH];         // A0 c-out (full)
__device__ __align__(16) float g_h0br[BB*HH];        // A1 h-out scratch (permuted+rounded)
__device__ unsigned g_cnt;
__device__ volatile unsigned g_gen;

// ---------------- helpers ----------------
__device__ __forceinline__ float tf32f(float x) {
    unsigned u; asm("cvt.rna.tf32.f32 %0, %1;" : "=r"(u) : "f"(x));
    return __uint_as_float(u);
}
__device__ __forceinline__ float sigf(float x) { return 1.f / (1.f + __expf(-x)); }

__device__ __forceinline__ void cpa(uint32_t ds, const float* gs) {
    asm volatile("cp.async.cg.shared.global [%0], [%1], 16;" :: "r"(ds), "l"(gs));
}

__device__ __forceinline__ void mma8(float* c, const unsigned* a, unsigned b0, unsigned b1) {
    asm volatile(
        "mma.sync.aligned.m16n8k8.row.col.f32.tf32.tf32.f32 "
        "{%0,%1,%2,%3}, {%4,%5,%6,%7}, {%8,%9}, {%0,%1,%2,%3};"
        : "+f"(c[0]), "+f"(c[1]), "+f"(c[2]), "+f"(c[3])
        : "r"(a[0]), "r"(a[1]), "r"(a[2]), "r"(a[3]), "r"(b0), "r"(b1));
}

// grid barrier: 128 CTAs, all resident (198KB smem -> 1 CTA/SM, 128 <= 148 SMs)
__device__ __forceinline__ void gsync() {
    __threadfence();
    __syncthreads();
    if (threadIdx.x == 0) {
        unsigned g = g_gen;
        if (atomicAdd(&g_cnt, 1u) == GRID - 1) {
            g_cnt = 0;
            __threadfence();
            g_gen = g + 1;
        } else {
            while (g_gen == g) { }
        }
    }
    __syncthreads();
    __threadfence();
}

// load one K-chunk: A 64 rows x 128 floats, W 64 rows x 128 floats
__device__ __forceinline__ void ld_chunk(uint32_t sb, int st, int kc,
    const float* xq, long xs, const float* hq, long hs, const float* wrow)
{
    const float* src; long rs; int ko;
    if (kc < 4) { src = xq; rs = xs; ko = kc * KC; }
    else        { src = hq; rs = hs; ko = (kc - 4) * KC; }
    uint32_t ab = sb + (uint32_t)st * STG_BY;
    const float* ws = wrow + kc * KC;
    int tid = threadIdx.x;
    #pragma unroll
    for (int i = 0; i < 16; ++i) {
        int idx = tid + i * NTHR;
        if (idx < 2048) {                      // A
            int r = idx >> 5, c4 = idx & 31;
            cpa(ab + (uint32_t)(r * 528 + c4 * 16), src + (long)r * rs + ko + c4 * 4);
        } else {                               // W
            int j2 = idx - 2048;
            int r = j2 >> 5, c4 = j2 & 31;
            cpa(ab + 33792u + (uint32_t)(r * 528 + c4 * 16), ws + (long)r * KK + c4 * 4);
        }
    }
    asm volatile("cp.async.commit_group;");
}

// one LSTM cell tile: gates[64 x 64] = [x;h] @ Wc^T + b, then elementwise.
// all row-indexed pointers pre-offset by m0 by the caller.
__device__ __noinline__ void cell_run(uint32_t sb, float* smf, int n0,
    const float* xq, long xs, const float* hq, long hs,
    const float* bias_n0,
    const float* cold, long cs,
    float* hfull, long hfs, float* hrd, long hrs, float* cdst, long cds,
    const float* wrow)
{
    int tid = threadIdx.x, w = tid >> 5, lane = tid & 31;
    int rb = lane >> 2, q = lane & 3;
    int wm = (w & 1) * 32, wn = (w >> 1) * 16;

    float acc[2][2][4];
    #pragma unroll
    for (int i = 0; i < 2; ++i)
        #pragma unroll
        for (int j = 0; j < 2; ++j)
            #pragma unroll
            for (int v = 0; v < 4; ++v) acc[i][j][v] = 0.f;

    ld_chunk(sb, 0, 0, xq, xs, hq, hs, wrow);
    ld_chunk(sb, 1, 1, xq, xs, hq, hs, wrow);

    int st = 0;
    #pragma unroll 1
    for (int kc = 0; kc < NKC; ++kc) {
        __syncthreads();                       // stage (kc+2)%3 free (compute kc-1 done)
        if (kc + 2 < NKC) {
            int s2 = st + 2; if (s2 >= 3) s2 -= 3;
            ld_chunk(sb, s2, kc + 2, xq, xs, hq, hs, wrow);
        }
        if (kc < NKC - 2)      asm volatile("cp.async.wait_group 2;");
        else if (kc == NKC - 2) asm volatile("cp.async.wait_group 1;");
        else                    asm volatile("cp.async.wait_group 0;");
        __syncthreads();                       // chunk kc visible to all threads

        const float* Ab = smf + st * STG_FL;
        const float* Wb = Ab + 64 * LDSD;
        const float* ap0 = Ab + (wm + rb) * LDSD + 2 * q;
        const float* bp0 = Wb + (wn + rb) * LDSD + 2 * q;
        #pragma unroll
        for (int ks = 0; ks < 16; ++ks) {
            unsigned a[2][4];
            #pragma unroll
            for (int i = 0; i < 2; ++i) {
                float2 lo = *(const float2*)(ap0 + i * 16 * LDSD + ks * 8);
                float2 hi = *(const float2*)(ap0 + i * 16 * LDSD + 8 * LDSD + ks * 8);
                a[i][0] = __float_as_uint(lo.x);
                a[i][1] = __float_as_uint(hi.x);
                a[i][2] = __float_as_uint(lo.y);
                a[i][3] = __float_as_uint(hi.y);
            }
            #pragma unroll
            for (int j = 0; j < 2; ++j) {
                float2 bv = *(const float2*)(bp0 + j * 8 * LDSD + ks * 8);
                unsigned b0 = __float_as_uint(bv.x), b1 = __float_as_uint(bv.y);
                mma8(acc[0][j], a[0], b0, b1);
                mma8(acc[1][j], a[1], b0, b1);
            }
        }
        ++st; if (st >= 3) st -= 3;
    }

    // elementwise LSTM: cols 4u..4u+3 = (i,f,g,o) of unit u; pair lanes via shfl_xor 1
    bool ev = !(q & 1);
    #pragma unroll
    for (int i = 0; i < 2; ++i) {
        #pragma unroll
        for (int j = 0; j < 2; ++j) {
            int ncl = wn + 8 * j + 2 * q;
            float b0 = g_bias[0][0] * 0.f + bias_n0[ncl];   // plain loads
            float b1 = bias_n0[ncl + 1];
            #pragma unroll
            for (int h = 0; h < 2; ++h) {
                float v0 = acc[i][j][2 * h] + b0;
                float v1 = acc[i][j][2 * h + 1] + b1;
                float p0 = __shfl_xor_sync(0xffffffffu, v0, 1);
                float p1 = __shfl_xor_sync(0xffffffffu, v1, 1);
                if (ev) {
                    float ig = v0, fg = v1, gg = p0, og = p1;
                    int mrow = wm + 16 * i + rb + 8 * h;
                    int u = (n0 + ncl) >> 2;
                    float co = cold ? __ldcg(cold + (long)mrow * cs + u) : 0.f;
                    float cn = sigf(fg) * co + sigf(ig) * tanhf(gg);
                    float hn = sigf(og) * tanhf(cn);
                    if (hfull) hfull[(long)mrow * hfs + u] = hn;
                    int ub = u & 7;
                    int up = (u & ~7) | ((ub < 4) ? 2 * ub : 2 * (ub - 4) + 1);
                    hrd[(long)mrow * hrs + up] = tf32f(hn);
                    cdst[(long)mrow * cds + u] = cn;
                }
            }
        }
    }
}

// ---------------- main persistent kernel ----------------
__global__ void __launch_bounds__(NTHR, 1) lstm_main(float* __restrict__ out) {
    extern __shared__ __align__(16) float smf[];
    uint32_t sb = (uint32_t)__cvta_generic_to_shared(smf);

    int tid = threadIdx.x;
    int cta = blockIdx.x;
    int grp = cta >> 6;
    int c = cta & 63;
    int m0 = (c & 1) * 64;
    int n0 = (c >> 1) * 64;
    const long TH = (long)TT * HH;
    float* outH0 = out + (long)m0 * TH;
    float* outM0 = out + O_M0 + (long)m0 * TH;
    long mo = (long)m0 * HH;

    #pragma unroll 1
    for (int ph = 0; ph <= 2 * TT; ++ph) {
        int t = ph >> 1;
        if (!(ph & 1)) {
            if (grp == 0) {
                if (t < TT)   // A0(t): x=h1r[0], h=H0r[:,t], c=0 -> h0ar,m0a
                    cell_run(sb, smf, n0,
                             g_h1r[0][t & 1] + mo, HH,
                             g_H0r + (long)t * HH + (long)m0 * TH, TH,
                             &g_bias[0][n0], nullptr, 0,
                             nullptr, 0, g_h0ar + mo, HH, g_m0a + mo, HH,
                             &g_Wc[0][n0][0]);
            } else if (t >= 1) {  // B1(t-1): x=h0br, h=h1r[1], c=m1[1]
                int tp = t - 1;
                cell_run(sb, smf, n0,
                         g_h0br + mo, HH, g_h1r[1][tp & 1] + mo, HH,
                         &g_bias[3][n0], g_m1[1] + mo, HH,
                         g_h1f[1] + mo, HH, g_h1r[1][(tp + 1) & 1] + mo, HH,
                         g_m1[1] + mo, HH, &g_Wc[3][n0][0]);
            }
        } else {
            if (grp == 0) {       // B0(t): x=h0ar, h=h1r[0], c=m1[0]
                cell_run(sb, smf, n0,
                         g_h0ar + mo, HH, g_h1r[0][t & 1] + mo, HH,
                         &g_bias[1][n0], g_m1[0] + mo, HH,
                         g_h1f[0] + mo, HH, g_h1r[0][(t + 1) & 1] + mo, HH,
                         g_m1[0] + mo, HH, &g_Wc[1][n0][0]);
            } else {              // A1(t): x=h1r[1], h=h0ar, c=m0a -> d_out + h0br
                cell_run(sb, smf, n0,
                         g_h1r[1][t & 1] + mo, HH, g_h0ar + mo, HH,
                         &g_bias[2][n0], g_m0a + mo, HH,
                         outH0 + (long)t * HH, TH, g_h0br + mo, HH,
                         outM0 + (long)t * HH, TH, &g_Wc[2][n0][0]);
            }
        }
        gsync();
    }

    // final H1f / M1f
    for (long idx = (long)cta * NTHR + tid; idx < 2L * BB * HH; idx += (long)GRID * NTHR) {
        int b = (int)(idx >> 10), l = (int)((idx >> 9) & 1), j = (int)(idx & 511);
        out[O_H1F + idx] = __ldcg(&g_h1f[l][b * HH + j]);
        out[O_M1F + idx] = __ldcg(&g_m1[l][b * HH + j]);
    }
}

// ---------------- prep kernels ----------------
// g_Wc[c][nr][k]: nr = 4*j+g (gate-interleaved), k position holds source feature inv(k)
__global__ void prep_w(const float* __restrict__ Wih, const float* __restrict__ Whh) {
    long i = (long)blockIdx.x * blockDim.x + threadIdx.x;
    if (i >= (long)4 * NGATE * KK) return;
    int k = (int)(i & 1023);
    long r = i >> 10;
    int nr = (int)(r & 2047);
    int cc = (int)(r >> 11);
    int g = nr & 3, j = nr >> 2;
    long srow = (long)cc * NGATE + g * HH + j;
    int kb = k & 7;
    int ks = (k & ~7) | ((kb >> 1) + ((kb & 1) ? 4 : 0));
    float v = (ks < HH) ? Wih[srow * HH + ks] : Whh[srow * HH + (ks - HH)];
    unsigned u; asm("cvt.rna.tf32.f32 %0, %1;" : "=r"(u) : "f"(v));
    ((float*)g_Wc)[i] = __uint_as_float(u);
}

__global__ void prep_x(const float* __restrict__ H0) {
    long i = (long)blockIdx.x * blockDim.x + threadIdx.x;
    if (i >= (long)BB * TT * HH) return;
    int h = (int)(i & 511);
    int hb = h & 7;
    long s = (i & ~511L) | (long)((h & ~7) | ((hb >> 1) + ((hb & 1) ? 4 : 0)));
    unsigned u; asm("cvt.rna.tf32.f32 %0, %1;" : "=r"(u) : "f"(H0[s]));
    g_H0r[i] = __uint_as_float(u);
}

__global__ void prep_misc(const float* __restrict__ bih, const float* __restrict__ bhh) {
    int i = blockIdx.x * blockDim.x + threadIdx.x;
    if (i < 2 * 2 * BB * HH) ((float*)g_h1r)[i] = 0.f;
    if (i < 2 * BB * HH) { ((float*)g_h1f)[i] = 0.f; ((float*)g_m1)[i] = 0.f; }
    if (i < 4 * NGATE) {
        int nr = i & 2047, cc = i >> 11;
        int g = nr & 3, j = nr >> 2;
        long s = (long)cc * NGATE + g * HH + j;
        ((float*)g_bias)[i] = bih[s] + bhh[s];
    }
    if (i == 0) { g_cnt = 0; g_gen = 0; }
}

// ---------------- launch ----------------
extern "C" void kernel_launch(void* const* d_in, const int* in_sizes, int n_in,
                              void* d_out, int out_size) {
    const float* H0  = (const float*)d_in[0];
    const float* Wih = (const float*)d_in[1];
    const float* Whh = (const float*)d_in[2];
    const float* bih = (const float*)d_in[3];
    const float* bhh = (const float*)d_in[4];
    float* out = (float*)d_out;

    prep_w<<<32768, 256>>>(Wih, Whh);
    prep_x<<<65536, 256>>>(H0);
    prep_misc<<<1024, 256>>>(bih, bhh);

    cudaFuncSetAttribute(lstm_main, cudaFuncAttributeMaxDynamicSharedMemorySize, SMEMB);
    lstm_main<<<GRID, NTHR, SMEMB>>>(out);
}

// round 6
// speedup vs baseline: 1.7007x; 1.5042x over previous
#include <cuda_runtime.h>
#include <cstdint>

#define TT 256
#define HH 512
#define BB 128
#define NGATE 2048
#define GRID 128
#define NTHR 256
#define KC 128                 // K per chunk
#define NKC 8
#define LDSD 136               // A row stride in floats (544B) -> conflict-free frags
#define STG_FL (64*LDSD)       // 8704 floats per A stage
#define STG_BY (STG_FL*4)      // 34816 B
#define SMEMB (3*STG_BY)       // 104448 B

#define O_H1F 16777216L
#define O_M0  16908288L
#define O_M1F 33685504L

// ---------------- device scratch ----------------
// W in per-warp fragment order: [cell][n0b(32)][kc(8)][wn4(4)][ks(16)][j(2)][lane(32)][2]
__device__ __align__(16) float g_Wf[4L*32*8*4*16*2*32*2];
__device__ __align__(16) float g_bias[4][NGATE];
__device__ __align__(16) float g_H0r[(long)BB*TT*HH];  // H0, k-permuted + tf32-rounded
__device__ __align__(16) float g_h1r[2][2][BB*HH];     // [layer][parity], permuted+rounded (MMA input)
__device__ __align__(16) float g_h1f[2][BB*HH];        // full precision (final output)
__device__ __align__(16) float g_m1[2][BB*HH];         // cell state, full precision
__device__ __align__(16) float g_h0ar[BB*HH];          // A0 h-out (permuted+rounded)
__device__ __align__(16) float g_m0a[BB*HH];           // A0 c-out (full)
__device__ __align__(16) float g_h0br[BB*HH];          // A1 h-out scratch (permuted+rounded)
__device__ unsigned g_cnt;
__device__ volatile unsigned g_gen;

// ---------------- helpers ----------------
__device__ __forceinline__ float tf32f(float x) {
    unsigned u; asm("cvt.rna.tf32.f32 %0, %1;" : "=r"(u) : "f"(x));
    return __uint_as_float(u);
}
__device__ __forceinline__ float sigf(float x) { return 1.f / (1.f + __expf(-x)); }

__device__ __forceinline__ void cpa(uint32_t ds, const float* gs) {
    asm volatile("cp.async.cg.shared.global [%0], [%1], 16;" :: "r"(ds), "l"(gs));
}
__device__ __forceinline__ void cpwait(int n) {
    if (n >= 2)      asm volatile("cp.async.wait_group 2;");
    else if (n == 1) asm volatile("cp.async.wait_group 1;");
    else             asm volatile("cp.async.wait_group 0;");
}

__device__ __forceinline__ void mma8(float* c, const unsigned* a, unsigned b0, unsigned b1) {
    asm volatile(
        "mma.sync.aligned.m16n8k8.row.col.f32.tf32.tf32.f32 "
        "{%0,%1,%2,%3}, {%4,%5,%6,%7}, {%8,%9}, {%0,%1,%2,%3};"
        : "+f"(c[0]), "+f"(c[1]), "+f"(c[2]), "+f"(c[3])
        : "r"(a[0]), "r"(a[1]), "r"(a[2]), "r"(a[3]), "r"(b0), "r"(b1));
}

// grid barrier: 128 CTAs <= 148 SMs, all resident -> deadlock-free
__device__ __forceinline__ void gsync() {
    __threadfence();
    __syncthreads();
    if (threadIdx.x == 0) {
        unsigned g = g_gen;
        if (atomicAdd(&g_cnt, 1u) == GRID - 1) {
            g_cnt = 0;
            __threadfence();
            g_gen = g + 1;
        } else {
            while (g_gen == g) { }
        }
    }
    __syncthreads();
    __threadfence();
}

// A chunk: 64 rows x 128 floats -> smem stage (linear rows, stride 544B)
__device__ __forceinline__ void ldA(uint32_t sb, int st, int kc,
    const float* xq, long xs, const float* hq, long hs)
{
    const float* src; long rs; int ko;
    if (kc < 4) { src = xq; rs = xs; ko = kc * KC; }
    else        { src = hq; rs = hs; ko = (kc - 4) * KC; }
    uint32_t ab = sb + (uint32_t)st * STG_BY;
    int tid = threadIdx.x;
    #pragma unroll
    for (int i = 0; i < 8; ++i) {
        int idx = tid + i * NTHR;            // 0..2047
        int r = idx >> 5, c4 = idx & 31;
        cpa(ab + (uint32_t)(r * 544 + c4 * 16), src + (long)r * rs + ko + c4 * 4);
    }
    asm volatile("cp.async.commit_group;");
}

// one LSTM cell tile: gates[64 x 64] = [x;h] @ W^T + b, then elementwise.
__device__ __noinline__ void cell_run(uint32_t sb, float* smf, int n0,
    const float* xq, long xs, const float* hq, long hs,
    const float* bias_n0,
    const float* cold, long cs,
    float* hfull, long hfs, float* hrd, long hrs, float* cdst, long cds,
    const float* wbase)
{
    int tid = threadIdx.x, w = tid >> 5, lane = tid & 31;
    int rb = lane >> 2, q = lane & 3;
    int wm = (w & 1) * 32;
    int wn4 = w >> 1;
    int wn = wn4 * 16;

    float acc[2][2][4];
    #pragma unroll
    for (int i = 0; i < 2; ++i)
        #pragma unroll
        for (int j = 0; j < 2; ++j)
            #pragma unroll
            for (int v = 0; v < 4; ++v) acc[i][j][v] = 0.f;

    float2 bA[8][2], bB[8][2];
    const float2* wlane = (const float2*)wbase + wn4 * 1024 + lane;

    // B half-chunk loader: half h of chunk kc -> buf
    #define LOADB(buf, kc_, h_) do {                                           \
        const float2* wp_ = wlane + (kc_) * 4096;                              \
        _Pragma("unroll")                                                      \
        for (int ks_ = 0; ks_ < 8; ++ks_) {                                    \
            _Pragma("unroll")                                                  \
            for (int j_ = 0; j_ < 2; ++j_)                                     \
                (buf)[ks_][j_] = wp_[(((h_) * 8 + ks_) * 2 + j_) * 32];        \
        }                                                                      \
    } while (0)

    #define COMP8(buf, Ab_, ksb_) do {                                         \
        const float* ap_ = (Ab_) + (wm + rb) * LDSD + 2 * q + (ksb_) * 8;      \
        _Pragma("unroll")                                                      \
        for (int ks_ = 0; ks_ < 8; ++ks_) {                                    \
            unsigned a_[2][4];                                                 \
            _Pragma("unroll")                                                  \
            for (int i_ = 0; i_ < 2; ++i_) {                                   \
                float2 lo_ = *(const float2*)(ap_ + i_ * 16 * LDSD + ks_ * 8); \
                float2 hi_ = *(const float2*)(ap_ + i_ * 16 * LDSD + 8 * LDSD + ks_ * 8); \
                a_[i_][0] = __float_as_uint(lo_.x);                            \
                a_[i_][1] = __float_as_uint(hi_.x);                            \
                a_[i_][2] = __float_as_uint(lo_.y);                            \
                a_[i_][3] = __float_as_uint(hi_.y);                            \
            }                                                                  \
            _Pragma("unroll")                                                  \
            for (int j_ = 0; j_ < 2; ++j_) {                                   \
                unsigned b0_ = __float_as_uint((buf)[ks_][j_].x);              \
                unsigned b1_ = __float_as_uint((buf)[ks_][j_].y);              \
                mma8(acc[0][j_], a_[0], b0_, b1_);                             \
                mma8(acc[1][j_], a_[1], b0_, b1_);                             \
            }                                                                  \
        }                                                                      \
    } while (0)

    ldA(sb, 0, 0, xq, xs, hq, hs);
    ldA(sb, 1, 1, xq, xs, hq, hs);
    LOADB(bA, 0, 0);

    int st = 0;
    #pragma unroll 1
    for (int kc = 0; kc < NKC; ++kc) {
        __syncthreads();                         // stage (st+2)%3 free
        if (kc + 2 < NKC) {
            int s2 = st + 2; if (s2 >= 3) s2 -= 3;
            ldA(sb, s2, kc + 2, xq, xs, hq, hs);
        }
        cpwait(NKC - kc - 1 >= 2 ? 2 : NKC - kc - 1);
        __syncthreads();                         // chunk kc visible

        const float* Ab = smf + st * STG_FL;
        LOADB(bB, kc, 1);                        // prefetch 2nd half of this chunk
        COMP8(bA, Ab, 0);
        if (kc + 1 < NKC) LOADB(bA, kc + 1, 0);  // prefetch 1st half of next chunk
        COMP8(bB, Ab, 8);
        ++st; if (st >= 3) st -= 3;
    }
    #undef LOADB
    #undef COMP8

    // elementwise LSTM: gate cols 4u..4u+3 = (i,f,g,o) of unit u; pair lanes via shfl_xor 1
    bool ev = !(q & 1);
    #pragma unroll
    for (int i = 0; i < 2; ++i) {
        #pragma unroll
        for (int j = 0; j < 2; ++j) {
            int ncl = wn + 8 * j + 2 * q;
            float b0 = bias_n0[ncl];
            float b1 = bias_n0[ncl + 1];
            #pragma unroll
            for (int h = 0; h < 2; ++h) {
                float v0 = acc[i][j][2 * h] + b0;
                float v1 = acc[i][j][2 * h + 1] + b1;
                float p0 = __shfl_xor_sync(0xffffffffu, v0, 1);
                float p1 = __shfl_xor_sync(0xffffffffu, v1, 1);
                if (ev) {
                    float ig = v0, fg = v1, gg = p0, og = p1;
                    int mrow = wm + 16 * i + rb + 8 * h;
                    int u = (n0 + ncl) >> 2;
                    float co = cold ? __ldcg(cold + (long)mrow * cs + u) : 0.f;
                    float cn = sigf(fg) * co + sigf(ig) * tanhf(gg);
                    float hn = sigf(og) * tanhf(cn);
                    if (hfull) hfull[(long)mrow * hfs + u] = hn;
                    int ub = u & 7;
                    int up = (u & ~7) | ((ub < 4) ? 2 * ub : 2 * (ub - 4) + 1);
                    hrd[(long)mrow * hrs + up] = tf32f(hn);
                    cdst[(long)mrow * cds + u] = cn;
                }
            }
        }
    }
}

// ---------------- main persistent kernel ----------------
__global__ void __launch_bounds__(NTHR, 1) lstm_main(float* __restrict__ out) {
    extern __shared__ __align__(16) float smf[];
    uint32_t sb = (uint32_t)__cvta_generic_to_shared(smf);

    int tid = threadIdx.x;
    int cta = blockIdx.x;
    int grp = cta >> 6;
    int c = cta & 63;
    int m0 = (c & 1) * 64;
    int n0b = c >> 1;
    int n0 = n0b * 64;
    const long TH = (long)TT * HH;
    float* outH0 = out + (long)m0 * TH;
    float* outM0 = out + O_M0 + (long)m0 * TH;
    long mo = (long)m0 * HH;

    const float* w0 = g_Wf + ((long)(0 * 32 + n0b)) * 65536;
    const float* w1 = g_Wf + ((long)(1 * 32 + n0b)) * 65536;
    const float* w2 = g_Wf + ((long)(2 * 32 + n0b)) * 65536;
    const float* w3 = g_Wf + ((long)(3 * 32 + n0b)) * 65536;

    #pragma unroll 1
    for (int ph = 0; ph <= 2 * TT; ++ph) {
        int t = ph >> 1;
        if (!(ph & 1)) {
            if (grp == 0) {
                if (t < TT)   // cell00(t): x=h1r[0], h=H0r[:,t], c=0 -> h0ar,m0a
                    cell_run(sb, smf, n0,
                             g_h1r[0][t & 1] + mo, HH,
                             g_H0r + (long)t * HH + (long)m0 * TH, TH,
                             &g_bias[0][n0], nullptr, 0,
                             nullptr, 0, g_h0ar + mo, HH, g_m0a + mo, HH, w0);
            } else if (t >= 1) {  // cell11(t-1): x=h0br, h=h1r[1], c=m1[1]
                int tp = t - 1;
                cell_run(sb, smf, n0,
                         g_h0br + mo, HH, g_h1r[1][tp & 1] + mo, HH,
                         &g_bias[3][n0], g_m1[1] + mo, HH,
                         g_h1f[1] + mo, HH, g_h1r[1][(tp + 1) & 1] + mo, HH,
                         g_m1[1] + mo, HH, w3);
            }
        } else {
            if (grp == 0) {       // cell01(t): x=h0ar, h=h1r[0], c=m1[0]
                cell_run(sb, smf, n0,
                         g_h0ar + mo, HH, g_h1r[0][t & 1] + mo, HH,
                         &g_bias[1][n0], g_m1[0] + mo, HH,
                         g_h1f[0] + mo, HH, g_h1r[0][(t + 1) & 1] + mo, HH,
                         g_m1[0] + mo, HH, w1);
            } else {              // cell10(t): x=h1r[1], h=h0ar, c=m0a -> d_out + h0br
                cell_run(sb, smf, n0,
                         g_h1r[1][t & 1] + mo, HH, g_h0ar + mo, HH,
                         &g_bias[2][n0], g_m0a + mo, HH,
                         outH0 + (long)t * HH, TH, g_h0br + mo, HH,
                         outM0 + (long)t * HH, TH, w2);
            }
        }
        gsync();
    }

    // final H1f / M1f
    for (long idx = (long)cta * NTHR + tid; idx < 2L * BB * HH; idx += (long)GRID * NTHR) {
        int b = (int)(idx >> 10), l = (int)((idx >> 9) & 1), j = (int)(idx & 511);
        out[O_H1F + idx] = __ldcg(&g_h1f[l][b * HH + j]);
        out[O_M1F + idx] = __ldcg(&g_m1[l][b * HH + j]);
    }
}

// ---------------- prep kernels ----------------
// fragment-order W: f bits = [cell(2)][n0b(5)][kc(3)][wn4(2)][ks(4)][j(1)][lane(5)][p(1)]
__global__ void prep_wf(const float* __restrict__ Wih, const float* __restrict__ Whh) {
    long f = (long)blockIdx.x * blockDim.x + threadIdx.x;
    if (f >= 8388608L) return;
    int p    = (int)(f & 1);
    int lane = (int)((f >> 1) & 31);
    int j    = (int)((f >> 6) & 1);
    int ks   = (int)((f >> 7) & 15);
    int wn4  = (int)((f >> 11) & 3);
    int kc   = (int)((f >> 13) & 7);
    int n0b  = (int)((f >> 16) & 31);
    int cell = (int)(f >> 21);
    int rb = lane >> 2, q = lane & 3;
    int row = n0b * 64 + wn4 * 16 + j * 8 + rb;     // gate-interleaved: row = 4*unit + gate
    int g = row & 3, jj = row >> 2;
    long srow = (long)cell * NGATE + g * HH + jj;
    int k = kc * KC + ks * 8 + q + p * 4;            // original k index
    float v = (k < HH) ? Wih[srow * HH + k] : Whh[srow * HH + (k - HH)];
    unsigned u; asm("cvt.rna.tf32.f32 %0, %1;" : "=r"(u) : "f"(v));
    g_Wf[f] = __uint_as_float(u);
}

__global__ void prep_x(const float* __restrict__ H0) {
    long i = (long)blockIdx.x * blockDim.x + threadIdx.x;
    if (i >= (long)BB * TT * HH) return;
    int h = (int)(i & 511);
    int hb = h & 7;
    long s = (i & ~511L) | (long)((h & ~7) | ((hb >> 1) + ((hb & 1) ? 4 : 0)));
    unsigned u; asm("cvt.rna.tf32.f32 %0, %1;" : "=r"(u) : "f"(H0[s]));
    g_H0r[i] = __uint_as_float(u);
}

__global__ void prep_misc(const float* __restrict__ bih, const float* __restrict__ bhh) {
    int i = blockIdx.x * blockDim.x + threadIdx.x;
    if (i < 2 * 2 * BB * HH) ((float*)g_h1r)[i] = 0.f;
    if (i < 2 * BB * HH) { ((float*)g_h1f)[i] = 0.f; ((float*)g_m1)[i] = 0.f; }
    if (i < 4 * NGATE) {
        int nr = i & 2047, cc = i >> 11;
        int g = nr & 3, j = nr >> 2;
        long s = (long)cc * NGATE + g * HH + j;
        ((float*)g_bias)[i] = bih[s] + bhh[s];
    }
    if (i == 0) { g_cnt = 0; g_gen = 0; }
}

// ---------------- launch ----------------
extern "C" void kernel_launch(void* const* d_in, const int* in_sizes, int n_in,
                              void* d_out, int out_size) {
    const float* H0  = (const float*)d_in[0];
    const float* Wih = (const float*)d_in[1];
    const float* Whh = (const float*)d_in[2];
    const float* bih = (const float*)d_in[3];
    const float* bhh = (const float*)d_in[4];
    float* out = (float*)d_out;

    prep_wf<<<32768, 256>>>(Wih, Whh);
    prep_x<<<65536, 256>>>(H0);
    prep_misc<<<1024, 256>>>(bih, bhh);

    cudaFuncSetAttribute(lstm_main, cudaFuncAttributeMaxDynamicSharedMemorySize, SMEMB);
    lstm_main<<<GRID, NTHR, SMEMB>>>(out);
}